// round 1
// baseline (speedup 1.0000x reference)
#include <cuda_runtime.h>
#include <cuda_bf16.h>
#include <math.h>

#define N_B 2
#define L_S 2048
#define EMB 1024
#define NH  16
#define HD  64
#define LP  65   // padded smem row for attention tiles

// Scratch (device globals — allocation-free rule)
__device__ float g_qp[N_B * NH * L_S * HD]; // [n,h,l,d]
__device__ float g_kp[N_B * NH * L_S * HD];
__device__ float g_vp[N_B * NH * L_S * HD];
__device__ float g_att[N_B * L_S * EMB];    // [n,l,e] pre-Wo attention output

// ---------------------------------------------------------------------------
// Kernel 1: per-head linear projections. Treat as M=N*L*H rows of dim 64.
// out[row_e] = sum_d x[row_d] * W[e][d]   (torch Linear: x @ W.T)
// blockIdx.y: 0 -> q (Wq), 1 -> k (Wk), 2 -> v (Wv)
// ---------------------------------------------------------------------------
__global__ __launch_bounds__(256) void proj_kernel(
    const float* __restrict__ q_in, const float* __restrict__ k_in,
    const float* __restrict__ v_in,
    const float* __restrict__ Wq, const float* __restrict__ Wk,
    const float* __restrict__ Wv)
{
    const float* x; const float* W; float* out;
    if (blockIdx.y == 0)      { x = q_in; W = Wq; out = g_qp; }
    else if (blockIdx.y == 1) { x = k_in; W = Wk; out = g_kp; }
    else                      { x = v_in; W = Wv; out = g_vp; }

    __shared__ float Ws[64][LP];
    __shared__ float Xs[64][LP];

    const int row0 = blockIdx.x * 64;   // global row in [0, N*L*H)
    const int tid  = threadIdx.x;

    // Load W (64x64)
    {
        int idx = tid * 4;              // 256*4 = 1024; need 4096 -> 4 iters
        #pragma unroll
        for (int it = 0; it < 4; it++, idx += 1024) {
            int r = idx >> 6, c = idx & 63;
            float4 w4 = *(const float4*)(W + idx);
            Ws[r][c] = w4.x; Ws[r][c+1] = w4.y; Ws[r][c+2] = w4.z; Ws[r][c+3] = w4.w;
        }
    }
    // Load X tile (64 rows x 64)
    {
        int idx = tid * 4;
        #pragma unroll
        for (int it = 0; it < 4; it++, idx += 1024) {
            int r = idx >> 6, c = idx & 63;
            int grow = row0 + r;
            int n   = grow >> 15;       // / (L*H) = 32768
            int rem = grow & 32767;
            int l   = rem >> 4;         // / NH
            int h   = rem & 15;
            float4 v4 = *(const float4*)(x + ((size_t)(n * L_S + l) * EMB + h * HD + c));
            Xs[r][c] = v4.x; Xs[r][c+1] = v4.y; Xs[r][c+2] = v4.z; Xs[r][c+3] = v4.w;
        }
    }
    __syncthreads();

    const int tx = tid & 15, ty = tid >> 4;
    float acc[4][4] = {};
    #pragma unroll 8
    for (int d = 0; d < 64; d++) {
        float xv[4], wv[4];
        #pragma unroll
        for (int i = 0; i < 4; i++) xv[i] = Xs[ty * 4 + i][d];
        #pragma unroll
        for (int j = 0; j < 4; j++) wv[j] = Ws[tx * 4 + j][d];
        #pragma unroll
        for (int i = 0; i < 4; i++)
            #pragma unroll
            for (int j = 0; j < 4; j++)
                acc[i][j] = fmaf(xv[i], wv[j], acc[i][j]);
    }

    #pragma unroll
    for (int i = 0; i < 4; i++) {
        int grow = row0 + ty * 4 + i;
        int n = grow >> 15, rem = grow & 32767;
        int l = rem >> 4,  h = rem & 15;
        float* dst = out + ((size_t)(n * NH + h) * L_S + l) * HD + tx * 4;
        #pragma unroll
        for (int j = 0; j < 4; j++) dst[j] = acc[i][j];
    }
}

// ---------------------------------------------------------------------------
// Kernel 2: flash attention per (n,h), 64-row Q tiles, fp32, online softmax.
// grid: (L/64, N*NH), block 256 (16x16 threads, 4x4 micro-tile)
// smem: Qs[64][LP] | Ks[64][LP] | VsT[64][LP] (e-major) | Ps[64][LP]
// ---------------------------------------------------------------------------
__global__ __launch_bounds__(256) void attn_kernel(const int* __restrict__ mask)
{
    extern __shared__ float sm[];
    float* Qs  = sm;
    float* Ks  = sm + 64 * LP;
    float* VsT = sm + 2 * 64 * LP;  // VsT[e*LP + c] = V[k0+c][e]
    float* Ps  = sm + 3 * 64 * LP;

    const int qt = blockIdx.x;            // 0..31
    const int nh = blockIdx.y;            // 0..31
    const int n  = nh >> 4, h = nh & 15;
    const int q0 = qt * 64;

    const float* Q = g_qp + (size_t)nh * L_S * HD;
    const float* K = g_kp + (size_t)nh * L_S * HD;
    const float* V = g_vp + (size_t)nh * L_S * HD;
    const int*   M = mask + (size_t)n * L_S * L_S;

    const int tid = threadIdx.x;
    const int tx = tid & 15, ty = tid >> 4;

    // Load Q tile
    {
        int idx = tid * 4;
        #pragma unroll
        for (int it = 0; it < 4; it++, idx += 1024) {
            int r = idx >> 6, c = idx & 63;
            float4 q4 = *(const float4*)(Q + (size_t)(q0 + r) * HD + c);
            Qs[r * LP + c] = q4.x; Qs[r * LP + c + 1] = q4.y;
            Qs[r * LP + c + 2] = q4.z; Qs[r * LP + c + 3] = q4.w;
        }
    }

    float m_[4], l_[4], o_[4][4] = {};
    #pragma unroll
    for (int i = 0; i < 4; i++) { m_[i] = -INFINITY; l_[i] = 0.f; }

    const float scale = 0.03125f;  // 1/sqrt(1024)

    for (int kt = 0; kt < L_S / 64; kt++) {
        const int k0 = kt * 64;
        // Load K tile and V tile (V transposed into VsT)
        {
            int idx = tid * 4;
            #pragma unroll
            for (int it = 0; it < 4; it++, idx += 1024) {
                int r = idx >> 6, c = idx & 63;
                float4 k4 = *(const float4*)(K + (size_t)(k0 + r) * HD + c);
                Ks[r * LP + c] = k4.x; Ks[r * LP + c + 1] = k4.y;
                Ks[r * LP + c + 2] = k4.z; Ks[r * LP + c + 3] = k4.w;
                float4 v4 = *(const float4*)(V + (size_t)(k0 + r) * HD + c);
                VsT[(c    ) * LP + r] = v4.x;
                VsT[(c + 1) * LP + r] = v4.y;
                VsT[(c + 2) * LP + r] = v4.z;
                VsT[(c + 3) * LP + r] = v4.w;
            }
        }
        __syncthreads();

        // GEMM1: S = Q K^T
        float s[4][4] = {};
        #pragma unroll 8
        for (int d = 0; d < 64; d++) {
            float qv[4], kv[4];
            #pragma unroll
            for (int i = 0; i < 4; i++) qv[i] = Qs[(ty * 4 + i) * LP + d];
            #pragma unroll
            for (int j = 0; j < 4; j++) kv[j] = Ks[(tx * 4 + j) * LP + d];
            #pragma unroll
            for (int i = 0; i < 4; i++)
                #pragma unroll
                for (int j = 0; j < 4; j++)
                    s[i][j] = fmaf(qv[i], kv[j], s[i][j]);
        }

        // scale + mask
        #pragma unroll
        for (int i = 0; i < 4; i++) {
            const int* mrow = M + (size_t)(q0 + ty * 4 + i) * L_S + k0 + tx * 4;
            #pragma unroll
            for (int j = 0; j < 4; j++) {
                float sc = s[i][j] * scale;
                if (mrow[j] == 0) sc = -1e20f;
                s[i][j] = sc;
            }
        }

        // online softmax update (row reductions across 16 tx lanes)
        #pragma unroll
        for (int i = 0; i < 4; i++) {
            float rm = fmaxf(fmaxf(s[i][0], s[i][1]), fmaxf(s[i][2], s[i][3]));
            #pragma unroll
            for (int off = 8; off; off >>= 1)
                rm = fmaxf(rm, __shfl_xor_sync(0xffffffffu, rm, off));
            float newm = fmaxf(m_[i], rm);
            float corr = __expf(m_[i] - newm);

            float rs = 0.f;
            #pragma unroll
            for (int j = 0; j < 4; j++) {
                float p = __expf(s[i][j] - newm);
                s[i][j] = p;
                rs += p;
            }
            #pragma unroll
            for (int off = 8; off; off >>= 1)
                rs += __shfl_xor_sync(0xffffffffu, rs, off);

            l_[i] = l_[i] * corr + rs;
            m_[i] = newm;
            #pragma unroll
            for (int j = 0; j < 4; j++) o_[i][j] *= corr;

            // stash P
            #pragma unroll
            for (int j = 0; j < 4; j++)
                Ps[(ty * 4 + i) * LP + tx * 4 + j] = s[i][j];
        }
        __syncthreads();

        // GEMM2: O += P V   (VsT is e-major)
        #pragma unroll 8
        for (int c = 0; c < 64; c++) {
            float pv[4], vv[4];
            #pragma unroll
            for (int i = 0; i < 4; i++) pv[i] = Ps[(ty * 4 + i) * LP + c];
            #pragma unroll
            for (int j = 0; j < 4; j++) vv[j] = VsT[(tx * 4 + j) * LP + c];
            #pragma unroll
            for (int i = 0; i < 4; i++)
                #pragma unroll
                for (int j = 0; j < 4; j++)
                    o_[i][j] = fmaf(pv[i], vv[j], o_[i][j]);
        }
        __syncthreads();
    }

    // finalize: divide by l and write [n, l, h*64+e]
    #pragma unroll
    for (int i = 0; i < 4; i++) {
        float inv = 1.f / l_[i];
        float* dst = g_att + ((size_t)(n * L_S + q0 + ty * 4 + i) * EMB) + h * HD + tx * 4;
        #pragma unroll
        for (int j = 0; j < 4; j++) dst[j] = o_[i][j] * inv;
    }
}

// ---------------------------------------------------------------------------
// Kernel 3: output projection  out[m][e] = sum_f g_att[m][f] * Wo[e][f] + bo[e]
// grid: (M/64, E/64), block 256 (16x16, 4x4 micro), K-tile 16
// ---------------------------------------------------------------------------
__global__ __launch_bounds__(256) void out_gemm(
    const float* __restrict__ Wo, const float* __restrict__ bo,
    float* __restrict__ out)
{
    __shared__ float As[64][17];
    __shared__ float Bs[16][68];

    const int m0 = blockIdx.x * 64;
    const int e0 = blockIdx.y * 64;
    const int tid = threadIdx.x;
    const int tx = tid & 15, ty = tid >> 4;

    float acc[4][4] = {};

    for (int f0 = 0; f0 < EMB; f0 += 16) {
        {
            int idx = tid * 4;           // 1024 elems exactly
            int r = idx >> 4, c = idx & 15;
            float4 a4 = *(const float4*)(g_att + (size_t)(m0 + r) * EMB + f0 + c);
            As[r][c] = a4.x; As[r][c+1] = a4.y; As[r][c+2] = a4.z; As[r][c+3] = a4.w;
            // B tile: Bs[f][e] = Wo[e0+e][f0+f]
            float4 b4 = *(const float4*)(Wo + (size_t)(e0 + r) * EMB + f0 + c);
            Bs[c  ][r] = b4.x; Bs[c+1][r] = b4.y; Bs[c+2][r] = b4.z; Bs[c+3][r] = b4.w;
        }
        __syncthreads();

        #pragma unroll
        for (int f = 0; f < 16; f++) {
            float av[4], bv[4];
            #pragma unroll
            for (int i = 0; i < 4; i++) av[i] = As[ty * 4 + i][f];
            #pragma unroll
            for (int j = 0; j < 4; j++) bv[j] = Bs[f][tx * 4 + j];
            #pragma unroll
            for (int i = 0; i < 4; i++)
                #pragma unroll
                for (int j = 0; j < 4; j++)
                    acc[i][j] = fmaf(av[i], bv[j], acc[i][j]);
        }
        __syncthreads();
    }

    #pragma unroll
    for (int i = 0; i < 4; i++) {
        float* dst = out + (size_t)(m0 + ty * 4 + i) * EMB + e0 + tx * 4;
        #pragma unroll
        for (int j = 0; j < 4; j++)
            dst[j] = acc[i][j] + bo[e0 + tx * 4 + j];
    }
}

// ---------------------------------------------------------------------------
extern "C" void kernel_launch(void* const* d_in, const int* in_sizes, int n_in,
                              void* d_out, int out_size)
{
    const float* values  = (const float*)d_in[0];
    const float* keys    = (const float*)d_in[1];
    const float* queries = (const float*)d_in[2];
    const int*   mask    = (const int*)  d_in[3];
    const float* Wv      = (const float*)d_in[4];
    const float* Wk      = (const float*)d_in[5];
    const float* Wq      = (const float*)d_in[6];
    const float* Wo      = (const float*)d_in[7];
    const float* bo      = (const float*)d_in[8];
    float* out = (float*)d_out;

    // projections: M = N*L*H = 65536 rows -> 1024 blocks, y = {q,k,v}
    proj_kernel<<<dim3(1024, 3), 256>>>(queries, keys, values, Wq, Wk, Wv);

    const int smem_attn = 4 * 64 * LP * sizeof(float);  // 66560 B
    cudaFuncSetAttribute(attn_kernel, cudaFuncAttributeMaxDynamicSharedMemorySize, smem_attn);
    attn_kernel<<<dim3(L_S / 64, N_B * NH), 256, smem_attn>>>(mask);

    out_gemm<<<dim3((N_B * L_S) / 64, EMB / 64), 256>>>(Wo, bo, out);
}

// round 2
// speedup vs baseline: 1.0008x; 1.0008x over previous
#include <cuda_runtime.h>
#include <cuda_bf16.h>
#include <math.h>

#define N_B 2
#define L_S 2048
#define EMB 1024
#define NH  16
#define HD  64
#define LP  65   // padded smem row for attention tiles

// Scratch (device globals — allocation-free rule)
__device__ float g_qp[N_B * NH * L_S * HD]; // [n,h,l,d]
__device__ float g_kp[N_B * NH * L_S * HD];
__device__ float g_vp[N_B * NH * L_S * HD];
__device__ float g_att[N_B * L_S * EMB];    // [n,l,e] pre-Wo attention output

// ---------------------------------------------------------------------------
// Kernel 1: per-head linear projections. Treat as M=N*L*H rows of dim 64.
// out[row_e] = sum_d x[row_d] * W[e][d]   (torch Linear: x @ W.T)
// blockIdx.y: 0 -> q (Wq), 1 -> k (Wk), 2 -> v (Wv)
// ---------------------------------------------------------------------------
__global__ __launch_bounds__(256) void proj_kernel(
    const float* __restrict__ q_in, const float* __restrict__ k_in,
    const float* __restrict__ v_in,
    const float* __restrict__ Wq, const float* __restrict__ Wk,
    const float* __restrict__ Wv)
{
    const float* x; const float* W; float* out;
    if (blockIdx.y == 0)      { x = q_in; W = Wq; out = g_qp; }
    else if (blockIdx.y == 1) { x = k_in; W = Wk; out = g_kp; }
    else                      { x = v_in; W = Wv; out = g_vp; }

    __shared__ float Ws[64][LP];
    __shared__ float Xs[64][LP];

    const int row0 = blockIdx.x * 64;   // global row in [0, N*L*H)
    const int tid  = threadIdx.x;

    // Load W (64x64)
    {
        int idx = tid * 4;              // 256*4 = 1024; need 4096 -> 4 iters
        #pragma unroll
        for (int it = 0; it < 4; it++, idx += 1024) {
            int r = idx >> 6, c = idx & 63;
            float4 w4 = *(const float4*)(W + idx);
            Ws[r][c] = w4.x; Ws[r][c+1] = w4.y; Ws[r][c+2] = w4.z; Ws[r][c+3] = w4.w;
        }
    }
    // Load X tile (64 rows x 64)
    {
        int idx = tid * 4;
        #pragma unroll
        for (int it = 0; it < 4; it++, idx += 1024) {
            int r = idx >> 6, c = idx & 63;
            int grow = row0 + r;
            int n   = grow >> 15;       // / (L*H) = 32768
            int rem = grow & 32767;
            int l   = rem >> 4;         // / NH
            int h   = rem & 15;
            float4 v4 = *(const float4*)(x + ((size_t)(n * L_S + l) * EMB + h * HD + c));
            Xs[r][c] = v4.x; Xs[r][c+1] = v4.y; Xs[r][c+2] = v4.z; Xs[r][c+3] = v4.w;
        }
    }
    __syncthreads();

    const int tx = tid & 15, ty = tid >> 4;
    float acc[4][4] = {};
    #pragma unroll 8
    for (int d = 0; d < 64; d++) {
        float xv[4], wv[4];
        #pragma unroll
        for (int i = 0; i < 4; i++) xv[i] = Xs[ty * 4 + i][d];
        #pragma unroll
        for (int j = 0; j < 4; j++) wv[j] = Ws[tx * 4 + j][d];
        #pragma unroll
        for (int i = 0; i < 4; i++)
            #pragma unroll
            for (int j = 0; j < 4; j++)
                acc[i][j] = fmaf(xv[i], wv[j], acc[i][j]);
    }

    #pragma unroll
    for (int i = 0; i < 4; i++) {
        int grow = row0 + ty * 4 + i;
        int n = grow >> 15, rem = grow & 32767;
        int l = rem >> 4,  h = rem & 15;
        float* dst = out + ((size_t)(n * NH + h) * L_S + l) * HD + tx * 4;
        #pragma unroll
        for (int j = 0; j < 4; j++) dst[j] = acc[i][j];
    }
}

// ---------------------------------------------------------------------------
// Kernel 2: flash attention per (n,h), 64-row Q tiles, fp32, online softmax.
// grid: (L/64, N*NH), block 256 (16x16 threads, 4x4 micro-tile)
// smem: Qs[64][LP] | Ks[64][LP] | VsT[64][LP] (e-major) | Ps[64][LP]
// ---------------------------------------------------------------------------
__global__ __launch_bounds__(256) void attn_kernel(const int* __restrict__ mask)
{
    extern __shared__ float sm[];
    float* Qs  = sm;
    float* Ks  = sm + 64 * LP;
    float* VsT = sm + 2 * 64 * LP;  // VsT[e*LP + c] = V[k0+c][e]
    float* Ps  = sm + 3 * 64 * LP;

    const int qt = blockIdx.x;            // 0..31
    const int nh = blockIdx.y;            // 0..31
    const int n  = nh >> 4, h = nh & 15;
    const int q0 = qt * 64;

    const float* Q = g_qp + (size_t)nh * L_S * HD;
    const float* K = g_kp + (size_t)nh * L_S * HD;
    const float* V = g_vp + (size_t)nh * L_S * HD;
    const int*   M = mask + (size_t)n * L_S * L_S;

    const int tid = threadIdx.x;
    const int tx = tid & 15, ty = tid >> 4;

    // Load Q tile
    {
        int idx = tid * 4;
        #pragma unroll
        for (int it = 0; it < 4; it++, idx += 1024) {
            int r = idx >> 6, c = idx & 63;
            float4 q4 = *(const float4*)(Q + (size_t)(q0 + r) * HD + c);
            Qs[r * LP + c] = q4.x; Qs[r * LP + c + 1] = q4.y;
            Qs[r * LP + c + 2] = q4.z; Qs[r * LP + c + 3] = q4.w;
        }
    }

    float m_[4], l_[4], o_[4][4] = {};
    #pragma unroll
    for (int i = 0; i < 4; i++) { m_[i] = -INFINITY; l_[i] = 0.f; }

    const float scale = 0.03125f;  // 1/sqrt(1024)

    for (int kt = 0; kt < L_S / 64; kt++) {
        const int k0 = kt * 64;
        // Load K tile and V tile (V transposed into VsT)
        {
            int idx = tid * 4;
            #pragma unroll
            for (int it = 0; it < 4; it++, idx += 1024) {
                int r = idx >> 6, c = idx & 63;
                float4 k4 = *(const float4*)(K + (size_t)(k0 + r) * HD + c);
                Ks[r * LP + c] = k4.x; Ks[r * LP + c + 1] = k4.y;
                Ks[r * LP + c + 2] = k4.z; Ks[r * LP + c + 3] = k4.w;
                float4 v4 = *(const float4*)(V + (size_t)(k0 + r) * HD + c);
                VsT[(c    ) * LP + r] = v4.x;
                VsT[(c + 1) * LP + r] = v4.y;
                VsT[(c + 2) * LP + r] = v4.z;
                VsT[(c + 3) * LP + r] = v4.w;
            }
        }
        __syncthreads();

        // GEMM1: S = Q K^T
        float s[4][4] = {};
        #pragma unroll 8
        for (int d = 0; d < 64; d++) {
            float qv[4], kv[4];
            #pragma unroll
            for (int i = 0; i < 4; i++) qv[i] = Qs[(ty * 4 + i) * LP + d];
            #pragma unroll
            for (int j = 0; j < 4; j++) kv[j] = Ks[(tx * 4 + j) * LP + d];
            #pragma unroll
            for (int i = 0; i < 4; i++)
                #pragma unroll
                for (int j = 0; j < 4; j++)
                    s[i][j] = fmaf(qv[i], kv[j], s[i][j]);
        }

        // scale + mask
        #pragma unroll
        for (int i = 0; i < 4; i++) {
            const int* mrow = M + (size_t)(q0 + ty * 4 + i) * L_S + k0 + tx * 4;
            #pragma unroll
            for (int j = 0; j < 4; j++) {
                float sc = s[i][j] * scale;
                if (mrow[j] == 0) sc = -1e20f;
                s[i][j] = sc;
            }
        }

        // online softmax update (row reductions across 16 tx lanes)
        #pragma unroll
        for (int i = 0; i < 4; i++) {
            float rm = fmaxf(fmaxf(s[i][0], s[i][1]), fmaxf(s[i][2], s[i][3]));
            #pragma unroll
            for (int off = 8; off; off >>= 1)
                rm = fmaxf(rm, __shfl_xor_sync(0xffffffffu, rm, off));
            float newm = fmaxf(m_[i], rm);
            float corr = __expf(m_[i] - newm);

            float rs = 0.f;
            #pragma unroll
            for (int j = 0; j < 4; j++) {
                float p = __expf(s[i][j] - newm);
                s[i][j] = p;
                rs += p;
            }
            #pragma unroll
            for (int off = 8; off; off >>= 1)
                rs += __shfl_xor_sync(0xffffffffu, rs, off);

            l_[i] = l_[i] * corr + rs;
            m_[i] = newm;
            #pragma unroll
            for (int j = 0; j < 4; j++) o_[i][j] *= corr;

            // stash P
            #pragma unroll
            for (int j = 0; j < 4; j++)
                Ps[(ty * 4 + i) * LP + tx * 4 + j] = s[i][j];
        }
        __syncthreads();

        // GEMM2: O += P V   (VsT is e-major)
        #pragma unroll 8
        for (int c = 0; c < 64; c++) {
            float pv[4], vv[4];
            #pragma unroll
            for (int i = 0; i < 4; i++) pv[i] = Ps[(ty * 4 + i) * LP + c];
            #pragma unroll
            for (int j = 0; j < 4; j++) vv[j] = VsT[(tx * 4 + j) * LP + c];
            #pragma unroll
            for (int i = 0; i < 4; i++)
                #pragma unroll
                for (int j = 0; j < 4; j++)
                    o_[i][j] = fmaf(pv[i], vv[j], o_[i][j]);
        }
        __syncthreads();
    }

    // finalize: divide by l and write [n, l, h*64+e]
    #pragma unroll
    for (int i = 0; i < 4; i++) {
        float inv = 1.f / l_[i];
        float* dst = g_att + ((size_t)(n * L_S + q0 + ty * 4 + i) * EMB) + h * HD + tx * 4;
        #pragma unroll
        for (int j = 0; j < 4; j++) dst[j] = o_[i][j] * inv;
    }
}

// ---------------------------------------------------------------------------
// Kernel 3: output projection  out[m][e] = sum_f g_att[m][f] * Wo[e][f] + bo[e]
// grid: (M/64, E/64), block 256 (16x16, 4x4 micro), K-tile 16
// ---------------------------------------------------------------------------
__global__ __launch_bounds__(256) void out_gemm(
    const float* __restrict__ Wo, const float* __restrict__ bo,
    float* __restrict__ out)
{
    __shared__ float As[64][17];
    __shared__ float Bs[16][68];

    const int m0 = blockIdx.x * 64;
    const int e0 = blockIdx.y * 64;
    const int tid = threadIdx.x;
    const int tx = tid & 15, ty = tid >> 4;

    float acc[4][4] = {};

    for (int f0 = 0; f0 < EMB; f0 += 16) {
        {
            int idx = tid * 4;           // 1024 elems exactly
            int r = idx >> 4, c = idx & 15;
            float4 a4 = *(const float4*)(g_att + (size_t)(m0 + r) * EMB + f0 + c);
            As[r][c] = a4.x; As[r][c+1] = a4.y; As[r][c+2] = a4.z; As[r][c+3] = a4.w;
            // B tile: Bs[f][e] = Wo[e0+e][f0+f]
            float4 b4 = *(const float4*)(Wo + (size_t)(e0 + r) * EMB + f0 + c);
            Bs[c  ][r] = b4.x; Bs[c+1][r] = b4.y; Bs[c+2][r] = b4.z; Bs[c+3][r] = b4.w;
        }
        __syncthreads();

        #pragma unroll
        for (int f = 0; f < 16; f++) {
            float av[4], bv[4];
            #pragma unroll
            for (int i = 0; i < 4; i++) av[i] = As[ty * 4 + i][f];
            #pragma unroll
            for (int j = 0; j < 4; j++) bv[j] = Bs[f][tx * 4 + j];
            #pragma unroll
            for (int i = 0; i < 4; i++)
                #pragma unroll
                for (int j = 0; j < 4; j++)
                    acc[i][j] = fmaf(av[i], bv[j], acc[i][j]);
        }
        __syncthreads();
    }

    #pragma unroll
    for (int i = 0; i < 4; i++) {
        float* dst = out + (size_t)(m0 + ty * 4 + i) * EMB + e0 + tx * 4;
        #pragma unroll
        for (int j = 0; j < 4; j++)
            dst[j] = acc[i][j] + bo[e0 + tx * 4 + j];
    }
}

// ---------------------------------------------------------------------------
extern "C" void kernel_launch(void* const* d_in, const int* in_sizes, int n_in,
                              void* d_out, int out_size)
{
    const float* values  = (const float*)d_in[0];
    const float* keys    = (const float*)d_in[1];
    const float* queries = (const float*)d_in[2];
    const int*   mask    = (const int*)  d_in[3];
    const float* Wv      = (const float*)d_in[4];
    const float* Wk      = (const float*)d_in[5];
    const float* Wq      = (const float*)d_in[6];
    const float* Wo      = (const float*)d_in[7];
    const float* bo      = (const float*)d_in[8];
    float* out = (float*)d_out;

    // projections: M = N*L*H = 65536 rows -> 1024 blocks, y = {q,k,v}
    proj_kernel<<<dim3(1024, 3), 256>>>(queries, keys, values, Wq, Wk, Wv);

    const int smem_attn = 4 * 64 * LP * sizeof(float);  // 66560 B
    cudaFuncSetAttribute(attn_kernel, cudaFuncAttributeMaxDynamicSharedMemorySize, smem_attn);
    attn_kernel<<<dim3(L_S / 64, N_B * NH), 256, smem_attn>>>(mask);

    out_gemm<<<dim3((N_B * L_S) / 64, EMB / 64), 256>>>(Wo, bo, out);
}

// round 3
// speedup vs baseline: 4.1266x; 4.1232x over previous
#include <cuda_runtime.h>
#include <cuda_fp16.h>
#include <math.h>
#include <stdint.h>

#define N_B 2
#define L_S 2048
#define EMB 1024
#define NH  16
#define HD  64
#define PITCH 72

// log2(e) / sqrt(EMB)
#define CEXP 0.045084220027780106f

__device__ __align__(128) __half g_qp[N_B * NH * L_S * HD]; // [n,h,l,d]
__device__ __align__(128) __half g_kp[N_B * NH * L_S * HD];
__device__ __align__(128) __half g_vp[N_B * NH * L_S * HD];
__device__ __align__(128) __half g_att[N_B * L_S * EMB];    // [n,l,e]
__device__ __align__(128) __half g_woh[EMB * EMB];

// ---------------------------------------------------------------------------
__device__ __forceinline__ float exp2_fast(float y) {
    y = fmaxf(y, -126.0f);
    float z = y + 12582912.0f;          // 1.5*2^23 round trick
    float n = z - 12582912.0f;
    float f = y - n;
    float p = 1.3333558e-3f;
    p = fmaf(p, f, 9.6181291e-3f);
    p = fmaf(p, f, 5.5504109e-2f);
    p = fmaf(p, f, 2.4022651e-1f);
    p = fmaf(p, f, 6.9314718e-1f);
    p = fmaf(p, f, 1.0f);
    int sb = (__float_as_int(z) << 23) + 0x3F800000;
    return p * __int_as_float(sb);
}

__device__ __forceinline__ void mma16816(float c[4],
    uint32_t a0, uint32_t a1, uint32_t a2, uint32_t a3,
    uint32_t b0, uint32_t b1)
{
    asm volatile(
        "mma.sync.aligned.m16n8k16.row.col.f32.f16.f16.f32 "
        "{%0,%1,%2,%3}, {%4,%5,%6,%7}, {%8,%9}, {%0,%1,%2,%3};\n"
        : "+f"(c[0]), "+f"(c[1]), "+f"(c[2]), "+f"(c[3])
        : "r"(a0), "r"(a1), "r"(a2), "r"(a3), "r"(b0), "r"(b1));
}

__device__ __forceinline__ uint32_t packh2(float a, float b) {
    union { __half2 h2; uint32_t u; } cvt;
    cvt.h2 = __floats2half2_rn(a, b);
    return cvt.u;
}

// ---------------------------------------------------------------------------
// Kernel 1: projections via fp16 mma. blockIdx.y: 0=q,1=k,2=v.
// Rows grow = n*32768 + l*16 + h. Block: 128 rows x 64 out, K=64.
// ---------------------------------------------------------------------------
__global__ __launch_bounds__(256) void proj_mma(
    const float* __restrict__ q_in, const float* __restrict__ k_in,
    const float* __restrict__ v_in,
    const float* __restrict__ Wq, const float* __restrict__ Wk,
    const float* __restrict__ Wv)
{
    const float* x; const float* W; __half* out;
    if (blockIdx.y == 0)      { x = q_in; W = Wq; out = g_qp; }
    else if (blockIdx.y == 1) { x = k_in; W = Wk; out = g_kp; }
    else                      { x = v_in; W = Wv; out = g_vp; }

    __shared__ __half Xs[128 * PITCH];
    __shared__ __half Ws[64 * PITCH];

    const int row0 = blockIdx.x * 128;
    const int tid  = threadIdx.x;

    #pragma unroll
    for (int it = 0; it < 4; it++) {
        int idx = tid * 4 + it * 1024;
        int r = idx >> 6, c = idx & 63;
        float4 w4 = *(const float4*)(W + idx);
        *(__half2*)&Ws[r * PITCH + c]     = __floats2half2_rn(w4.x, w4.y);
        *(__half2*)&Ws[r * PITCH + c + 2] = __floats2half2_rn(w4.z, w4.w);
    }
    #pragma unroll
    for (int it = 0; it < 8; it++) {
        int idx = tid * 4 + it * 1024;
        int r = idx >> 6, c = idx & 63;
        int grow = row0 + r;
        int n = grow >> 15, rem = grow & 32767;
        int l = rem >> 4, h = rem & 15;
        float4 v4 = *(const float4*)(x + ((size_t)(n * L_S + l) * EMB + h * HD + c));
        *(__half2*)&Xs[r * PITCH + c]     = __floats2half2_rn(v4.x, v4.y);
        *(__half2*)&Xs[r * PITCH + c + 2] = __floats2half2_rn(v4.z, v4.w);
    }
    __syncthreads();

    const int warp = tid >> 5, lane = tid & 31;
    const int g = lane >> 2, t4 = lane & 3;
    const int mw = warp * 16;

    uint32_t a[4][4];
    #pragma unroll
    for (int kc = 0; kc < 4; kc++) {
        a[kc][0] = *(const uint32_t*)&Xs[(mw + g    ) * PITCH + kc * 16 + 2 * t4];
        a[kc][1] = *(const uint32_t*)&Xs[(mw + g + 8) * PITCH + kc * 16 + 2 * t4];
        a[kc][2] = *(const uint32_t*)&Xs[(mw + g    ) * PITCH + kc * 16 + 2 * t4 + 8];
        a[kc][3] = *(const uint32_t*)&Xs[(mw + g + 8) * PITCH + kc * 16 + 2 * t4 + 8];
    }

    float o[8][4];
    #pragma unroll
    for (int nt = 0; nt < 8; nt++) { o[nt][0]=o[nt][1]=o[nt][2]=o[nt][3]=0.f; }

    #pragma unroll
    for (int nt = 0; nt < 8; nt++)
        #pragma unroll
        for (int kc = 0; kc < 4; kc++) {
            uint32_t b0 = *(const uint32_t*)&Ws[(nt * 8 + g) * PITCH + kc * 16 + 2 * t4];
            uint32_t b1 = *(const uint32_t*)&Ws[(nt * 8 + g) * PITCH + kc * 16 + 2 * t4 + 8];
            mma16816(o[nt], a[kc][0], a[kc][1], a[kc][2], a[kc][3], b0, b1);
        }

    #pragma unroll
    for (int nt = 0; nt < 8; nt++) {
        int e = nt * 8 + 2 * t4;
        int grow = row0 + mw + g;
        int n = grow >> 15, rem = grow & 32767;
        int l = rem >> 4, h = rem & 15;
        *(__half2*)(out + ((size_t)(n * NH + h) * L_S + l) * HD + e)
            = __floats2half2_rn(o[nt][0], o[nt][1]);
        grow += 8; n = grow >> 15; rem = grow & 32767; l = rem >> 4; h = rem & 15;
        *(__half2*)(out + ((size_t)(n * NH + h) * L_S + l) * HD + e)
            = __floats2half2_rn(o[nt][2], o[nt][3]);
    }
}

// ---------------------------------------------------------------------------
__global__ __launch_bounds__(256) void wo_cvt(const float* __restrict__ w)
{
    int i = (blockIdx.x * 256 + threadIdx.x) * 4;
    float4 v = *(const float4*)(w + i);
    *(__half2*)(g_woh + i)     = __floats2half2_rn(v.x, v.y);
    *(__half2*)(g_woh + i + 2) = __floats2half2_rn(v.z, v.w);
}

// ---------------------------------------------------------------------------
// Kernel 2: flash attention, fp16 mma. grid (nh=32, qt=16), block 256.
// BM=128 q rows, BN=64 keys/iter, D=64.
// ---------------------------------------------------------------------------
__global__ __launch_bounds__(256) void attn2(const int* __restrict__ mask)
{
    __shared__ __half Qs[128 * PITCH];
    __shared__ __half Ks[64 * PITCH];
    __shared__ __half Vs[64 * PITCH];   // [key][e]
    __shared__ __half VsT[64 * PITCH];  // [e][key]

    const int nh = blockIdx.x;
    const int qt = blockIdx.y;
    const int n  = nh >> 4, h = nh & 15;
    const int q0 = qt * 128;

    const __half* Qg = g_qp + (size_t)nh * L_S * HD;
    const __half* Kg = g_kp + (size_t)nh * L_S * HD;
    const __half* Vg = g_vp + (size_t)nh * L_S * HD;
    const int*    Mb = mask + (size_t)n * L_S * L_S;

    const int tid = threadIdx.x;
    const int warp = tid >> 5, lane = tid & 31;
    const int g = lane >> 2, t4 = lane & 3;
    const int mw = warp * 16;

    #pragma unroll
    for (int it = 0; it < 4; it++) {
        int u = tid + it * 256;
        int r = u >> 3, cg = (u & 7) * 8;
        *(uint4*)&Qs[r * PITCH + cg] = *(const uint4*)&Qg[(size_t)(q0 + r) * HD + cg];
    }
    __syncthreads();

    uint32_t qa[4][4];
    #pragma unroll
    for (int kc = 0; kc < 4; kc++) {
        qa[kc][0] = *(const uint32_t*)&Qs[(mw + g    ) * PITCH + kc * 16 + 2 * t4];
        qa[kc][1] = *(const uint32_t*)&Qs[(mw + g + 8) * PITCH + kc * 16 + 2 * t4];
        qa[kc][2] = *(const uint32_t*)&Qs[(mw + g    ) * PITCH + kc * 16 + 2 * t4 + 8];
        qa[kc][3] = *(const uint32_t*)&Qs[(mw + g + 8) * PITCH + kc * 16 + 2 * t4 + 8];
    }

    float o[8][4];
    #pragma unroll
    for (int ne = 0; ne < 8; ne++) { o[ne][0]=o[ne][1]=o[ne][2]=o[ne][3]=0.f; }
    float mr0 = -1e30f, mr1 = -1e30f, l0 = 0.f, l1 = 0.f;

    for (int kt = 0; kt < L_S / 64; kt++) {
        const int k0 = kt * 64;

        #pragma unroll
        for (int it = 0; it < 4; it++) {
            int u = tid + it * 256;
            if (u < 512) {
                int r = u >> 3, cg = (u & 7) * 8;
                *(uint4*)&Ks[r * PITCH + cg] = *(const uint4*)&Kg[(size_t)(k0 + r) * HD + cg];
            } else {
                int u2 = u - 512;
                int r = u2 >> 3, cg = (u2 & 7) * 8;
                *(uint4*)&Vs[r * PITCH + cg] = *(const uint4*)&Vg[(size_t)(k0 + r) * HD + cg];
            }
        }
        __syncthreads();

        // transpose Vs[key][e] -> VsT[e][key]
        #pragma unroll
        for (int it = 0; it < 2; it++) {
            int u = tid + it * 256;
            int e = u & 63, rg = u >> 6;   // rg 0..7
            __half tmp[8];
            #pragma unroll
            for (int j = 0; j < 8; j++) tmp[j] = Vs[(rg * 8 + j) * PITCH + e];
            *(uint4*)&VsT[e * PITCH + rg * 8] = *(const uint4*)tmp;
        }

        // GEMM1: S = Q K^T (raw scores)
        float s[8][4];
        #pragma unroll
        for (int nt = 0; nt < 8; nt++) {
            s[nt][0]=s[nt][1]=s[nt][2]=s[nt][3]=0.f;
            #pragma unroll
            for (int kc = 0; kc < 4; kc++) {
                uint32_t b0 = *(const uint32_t*)&Ks[(nt * 8 + g) * PITCH + kc * 16 + 2 * t4];
                uint32_t b1 = *(const uint32_t*)&Ks[(nt * 8 + g) * PITCH + kc * 16 + 2 * t4 + 8];
                mma16816(s[nt], qa[kc][0], qa[kc][1], qa[kc][2], qa[kc][3], b0, b1);
            }
        }

        // mask
        #pragma unroll
        for (int nt = 0; nt < 8; nt++) {
            int col = k0 + nt * 8 + 2 * t4;
            int2 mA = *(const int2*)(Mb + (size_t)(q0 + mw + g    ) * L_S + col);
            int2 mB = *(const int2*)(Mb + (size_t)(q0 + mw + g + 8) * L_S + col);
            if (mA.x == 0) s[nt][0] = -1e20f;
            if (mA.y == 0) s[nt][1] = -1e20f;
            if (mB.x == 0) s[nt][2] = -1e20f;
            if (mB.y == 0) s[nt][3] = -1e20f;
        }

        // online softmax (rows g, g+8)
        float mx0 = s[0][0], mx1 = s[0][2];
        #pragma unroll
        for (int nt = 0; nt < 8; nt++) {
            mx0 = fmaxf(mx0, fmaxf(s[nt][0], s[nt][1]));
            mx1 = fmaxf(mx1, fmaxf(s[nt][2], s[nt][3]));
        }
        mx0 = fmaxf(mx0, __shfl_xor_sync(0xffffffffu, mx0, 1));
        mx0 = fmaxf(mx0, __shfl_xor_sync(0xffffffffu, mx0, 2));
        mx1 = fmaxf(mx1, __shfl_xor_sync(0xffffffffu, mx1, 1));
        mx1 = fmaxf(mx1, __shfl_xor_sync(0xffffffffu, mx1, 2));

        float mn0 = fmaxf(mr0, mx0), mn1 = fmaxf(mr1, mx1);
        float c0 = exp2_fast((mr0 - mn0) * CEXP);
        float c1 = exp2_fast((mr1 - mn1) * CEXP);
        mr0 = mn0; mr1 = mn1;

        float sum0 = 0.f, sum1 = 0.f;
        #pragma unroll
        for (int nt = 0; nt < 8; nt++) {
            s[nt][0] = exp2_fast((s[nt][0] - mn0) * CEXP); sum0 += s[nt][0];
            s[nt][1] = exp2_fast((s[nt][1] - mn0) * CEXP); sum0 += s[nt][1];
            s[nt][2] = exp2_fast((s[nt][2] - mn1) * CEXP); sum1 += s[nt][2];
            s[nt][3] = exp2_fast((s[nt][3] - mn1) * CEXP); sum1 += s[nt][3];
        }
        sum0 += __shfl_xor_sync(0xffffffffu, sum0, 1);
        sum0 += __shfl_xor_sync(0xffffffffu, sum0, 2);
        sum1 += __shfl_xor_sync(0xffffffffu, sum1, 1);
        sum1 += __shfl_xor_sync(0xffffffffu, sum1, 2);
        l0 = l0 * c0 + sum0;
        l1 = l1 * c1 + sum1;

        #pragma unroll
        for (int ne = 0; ne < 8; ne++) {
            o[ne][0] *= c0; o[ne][1] *= c0;
            o[ne][2] *= c1; o[ne][3] *= c1;
        }

        // P fragments from registers
        uint32_t pa[4][4];
        #pragma unroll
        for (int kc = 0; kc < 4; kc++) {
            pa[kc][0] = packh2(s[2 * kc    ][0], s[2 * kc    ][1]);
            pa[kc][1] = packh2(s[2 * kc    ][2], s[2 * kc    ][3]);
            pa[kc][2] = packh2(s[2 * kc + 1][0], s[2 * kc + 1][1]);
            pa[kc][3] = packh2(s[2 * kc + 1][2], s[2 * kc + 1][3]);
        }

        __syncthreads();  // VsT writes visible; Ks/Vs reads done before next load

        // GEMM2: O += P V
        #pragma unroll
        for (int ne = 0; ne < 8; ne++)
            #pragma unroll
            for (int kc = 0; kc < 4; kc++) {
                uint32_t b0 = *(const uint32_t*)&VsT[(ne * 8 + g) * PITCH + kc * 16 + 2 * t4];
                uint32_t b1 = *(const uint32_t*)&VsT[(ne * 8 + g) * PITCH + kc * 16 + 2 * t4 + 8];
                mma16816(o[ne], pa[kc][0], pa[kc][1], pa[kc][2], pa[kc][3], b0, b1);
            }
    }

    float inv0 = 1.f / l0, inv1 = 1.f / l1;
    int row = q0 + mw + g;
    __half* base0 = g_att + ((size_t)n * L_S + row) * EMB + h * HD;
    __half* base1 = base0 + (size_t)8 * EMB;
    #pragma unroll
    for (int ne = 0; ne < 8; ne++) {
        int e = ne * 8 + 2 * t4;
        *(__half2*)(base0 + e) = __floats2half2_rn(o[ne][0] * inv0, o[ne][1] * inv0);
        *(__half2*)(base1 + e) = __floats2half2_rn(o[ne][2] * inv1, o[ne][3] * inv1);
    }
}

// ---------------------------------------------------------------------------
// Kernel 3: out projection, fp16 mma. grid (32 m-tiles, 16 e-tiles).
// out[m][e] = sum_f g_att[m][f] * Wo[e][f] + bo[e]
// ---------------------------------------------------------------------------
__global__ __launch_bounds__(256) void out_mma(
    const float* __restrict__ bo, float* __restrict__ out)
{
    __shared__ __half As[128 * PITCH];
    __shared__ __half Bs[64 * PITCH];

    const int m0 = blockIdx.x * 128;
    const int e0 = blockIdx.y * 64;
    const int tid = threadIdx.x;
    const int warp = tid >> 5, lane = tid & 31;
    const int g = lane >> 2, t4 = lane & 3;
    const int mw = warp * 16;

    float o[8][4];
    #pragma unroll
    for (int nt = 0; nt < 8; nt++) { o[nt][0]=o[nt][1]=o[nt][2]=o[nt][3]=0.f; }

    for (int f0 = 0; f0 < EMB; f0 += 64) {
        #pragma unroll
        for (int it = 0; it < 4; it++) {
            int u = tid + it * 256;
            int r = u >> 3, cg = (u & 7) * 8;
            *(uint4*)&As[r * PITCH + cg] =
                *(const uint4*)&g_att[(size_t)(m0 + r) * EMB + f0 + cg];
        }
        #pragma unroll
        for (int it = 0; it < 2; it++) {
            int u = tid + it * 256;
            int r = u >> 3, cg = (u & 7) * 8;
            *(uint4*)&Bs[r * PITCH + cg] =
                *(const uint4*)&g_woh[(size_t)(e0 + r) * EMB + f0 + cg];
        }
        __syncthreads();

        uint32_t a[4][4];
        #pragma unroll
        for (int kc = 0; kc < 4; kc++) {
            a[kc][0] = *(const uint32_t*)&As[(mw + g    ) * PITCH + kc * 16 + 2 * t4];
            a[kc][1] = *(const uint32_t*)&As[(mw + g + 8) * PITCH + kc * 16 + 2 * t4];
            a[kc][2] = *(const uint32_t*)&As[(mw + g    ) * PITCH + kc * 16 + 2 * t4 + 8];
            a[kc][3] = *(const uint32_t*)&As[(mw + g + 8) * PITCH + kc * 16 + 2 * t4 + 8];
        }
        #pragma unroll
        for (int nt = 0; nt < 8; nt++)
            #pragma unroll
            for (int kc = 0; kc < 4; kc++) {
                uint32_t b0 = *(const uint32_t*)&Bs[(nt * 8 + g) * PITCH + kc * 16 + 2 * t4];
                uint32_t b1 = *(const uint32_t*)&Bs[(nt * 8 + g) * PITCH + kc * 16 + 2 * t4 + 8];
                mma16816(o[nt], a[kc][0], a[kc][1], a[kc][2], a[kc][3], b0, b1);
            }
        __syncthreads();
    }

    #pragma unroll
    for (int nt = 0; nt < 8; nt++) {
        int e = e0 + nt * 8 + 2 * t4;
        float b0v = bo[e], b1v = bo[e + 1];
        float2* d0 = (float2*)(out + (size_t)(m0 + mw + g    ) * EMB + e);
        float2* d1 = (float2*)(out + (size_t)(m0 + mw + g + 8) * EMB + e);
        *d0 = make_float2(o[nt][0] + b0v, o[nt][1] + b1v);
        *d1 = make_float2(o[nt][2] + b0v, o[nt][3] + b1v);
    }
}

// ---------------------------------------------------------------------------
extern "C" void kernel_launch(void* const* d_in, const int* in_sizes, int n_in,
                              void* d_out, int out_size)
{
    const float* values  = (const float*)d_in[0];
    const float* keys    = (const float*)d_in[1];
    const float* queries = (const float*)d_in[2];
    const int*   mask    = (const int*)  d_in[3];
    const float* Wv      = (const float*)d_in[4];
    const float* Wk      = (const float*)d_in[5];
    const float* Wq      = (const float*)d_in[6];
    const float* Wo      = (const float*)d_in[7];
    const float* bo      = (const float*)d_in[8];
    float* out = (float*)d_out;

    proj_mma<<<dim3(512, 3), 256>>>(queries, keys, values, Wq, Wk, Wv);
    wo_cvt<<<1024, 256>>>(Wo);
    attn2<<<dim3(N_B * NH, L_S / 128), 256>>>(mask);
    out_mma<<<dim3((N_B * L_S) / 128, EMB / 64), 256>>>(bo, out);
}

// round 4
// speedup vs baseline: 5.5328x; 1.3407x over previous
#include <cuda_runtime.h>
#include <cuda_fp16.h>
#include <math.h>
#include <stdint.h>

#define N_B 2
#define L_S 2048
#define EMB 1024
#define NH  16
#define HD  64
#define PITCH 72

// log2(e) / sqrt(EMB)
#define CEXP 0.045084220027780106f

__device__ __align__(128) __half g_qp[N_B * NH * L_S * HD]; // [n,h,l,d]
__device__ __align__(128) __half g_kp[N_B * NH * L_S * HD];
__device__ __align__(128) __half g_vp[N_B * NH * L_S * HD];
__device__ __align__(128) __half g_att[N_B * L_S * EMB];    // [n,l,e]
__device__ __align__(128) __half g_woh[EMB * EMB];
__device__ __align__(128) uint32_t g_mpack[N_B * L_S * 64]; // packed mask bits
__device__ unsigned char g_mflag[N_B * 32 * 32];            // all-ones flag per 64x64 tile

// ---------------------------------------------------------------------------
__device__ __forceinline__ float exp2_fast(float y) {
    y = fmaxf(y, -126.0f);
    float z = y + 12582912.0f;          // 1.5*2^23 round trick
    float n = z - 12582912.0f;
    float f = y - n;
    float p = 1.3333558e-3f;
    p = fmaf(p, f, 9.6181291e-3f);
    p = fmaf(p, f, 5.5504109e-2f);
    p = fmaf(p, f, 2.4022651e-1f);
    p = fmaf(p, f, 6.9314718e-1f);
    p = fmaf(p, f, 1.0f);
    int sb = (__float_as_int(z) << 23) + 0x3F800000;
    return p * __int_as_float(sb);
}

__device__ __forceinline__ void mma16816(float c[4],
    uint32_t a0, uint32_t a1, uint32_t a2, uint32_t a3,
    uint32_t b0, uint32_t b1)
{
    asm volatile(
        "mma.sync.aligned.m16n8k16.row.col.f32.f16.f16.f32 "
        "{%0,%1,%2,%3}, {%4,%5,%6,%7}, {%8,%9}, {%0,%1,%2,%3};\n"
        : "+f"(c[0]), "+f"(c[1]), "+f"(c[2]), "+f"(c[3])
        : "r"(a0), "r"(a1), "r"(a2), "r"(a3), "r"(b0), "r"(b1));
}

__device__ __forceinline__ uint32_t packh2(float a, float b) {
    union { __half2 h2; uint32_t u; } cvt;
    cvt.h2 = __floats2half2_rn(a, b);
    return cvt.u;
}

__device__ __forceinline__ void ldsm_x4(uint32_t& r0, uint32_t& r1,
                                        uint32_t& r2, uint32_t& r3, const __half* p)
{
    uint32_t a = (uint32_t)__cvta_generic_to_shared(p);
    asm volatile("ldmatrix.sync.aligned.m8n8.x4.shared.b16 {%0,%1,%2,%3}, [%4];\n"
                 : "=r"(r0), "=r"(r1), "=r"(r2), "=r"(r3) : "r"(a));
}

__device__ __forceinline__ void ldsm_x4_t(uint32_t& r0, uint32_t& r1,
                                          uint32_t& r2, uint32_t& r3, const __half* p)
{
    uint32_t a = (uint32_t)__cvta_generic_to_shared(p);
    asm volatile("ldmatrix.sync.aligned.m8n8.x4.trans.shared.b16 {%0,%1,%2,%3}, [%4];\n"
                 : "=r"(r0), "=r"(r1), "=r"(r2), "=r"(r3) : "r"(a));
}

__device__ __forceinline__ void cp16(__half* s, const __half* g) {
    uint32_t a = (uint32_t)__cvta_generic_to_shared(s);
    asm volatile("cp.async.ca.shared.global [%0], [%1], 16;\n" :: "r"(a), "l"(g));
}
__device__ __forceinline__ void cp_commit() {
    asm volatile("cp.async.commit_group;\n");
}
template<int N> __device__ __forceinline__ void cp_wait() {
    asm volatile("cp.async.wait_group %0;\n" :: "n"(N));
}

// ---------------------------------------------------------------------------
// Mask preprocessing
// ---------------------------------------------------------------------------
__global__ __launch_bounds__(256) void mask_pack(const int* __restrict__ mask)
{
    int w = blockIdx.x * 256 + threadIdx.x;      // 0 .. N_B*L_S*64-1
    const int* src = mask + (size_t)w * 32;
    uint32_t bits = 0;
    #pragma unroll
    for (int i = 0; i < 8; i++) {
        int4 v = *(const int4*)(src + i * 4);
        bits |= (v.x != 0 ? 1u : 0u) << (i * 4);
        bits |= (v.y != 0 ? 1u : 0u) << (i * 4 + 1);
        bits |= (v.z != 0 ? 1u : 0u) << (i * 4 + 2);
        bits |= (v.w != 0 ? 1u : 0u) << (i * 4 + 3);
    }
    g_mpack[w] = bits;
}

__global__ __launch_bounds__(128) void mask_flag()
{
    // one block per 64x64 tile: bid -> n, qt, kt
    int bid = blockIdx.x;
    int n = bid >> 10, qt = (bid >> 5) & 31, kt = bid & 31;
    int row = qt * 64 + (threadIdx.x >> 1);
    int word = kt * 2 + (threadIdx.x & 1);
    uint32_t v = g_mpack[((size_t)n * L_S + row) * 64 + word];
    int all1 = __syncthreads_and(v == 0xFFFFFFFFu);
    if (threadIdx.x == 0) g_mflag[bid] = (unsigned char)all1;
}

// ---------------------------------------------------------------------------
// Kernel 1: projections via fp16 mma. blockIdx.y: 0=q,1=k,2=v.
// ---------------------------------------------------------------------------
__global__ __launch_bounds__(256) void proj_mma(
    const float* __restrict__ q_in, const float* __restrict__ k_in,
    const float* __restrict__ v_in,
    const float* __restrict__ Wq, const float* __restrict__ Wk,
    const float* __restrict__ Wv)
{
    const float* x; const float* W; __half* out;
    if (blockIdx.y == 0)      { x = q_in; W = Wq; out = g_qp; }
    else if (blockIdx.y == 1) { x = k_in; W = Wk; out = g_kp; }
    else                      { x = v_in; W = Wv; out = g_vp; }

    __shared__ __half Xs[128 * PITCH];
    __shared__ __half Ws[64 * PITCH];

    const int row0 = blockIdx.x * 128;
    const int tid  = threadIdx.x;

    #pragma unroll
    for (int it = 0; it < 4; it++) {
        int idx = tid * 4 + it * 1024;
        int r = idx >> 6, c = idx & 63;
        float4 w4 = *(const float4*)(W + idx);
        *(__half2*)&Ws[r * PITCH + c]     = __floats2half2_rn(w4.x, w4.y);
        *(__half2*)&Ws[r * PITCH + c + 2] = __floats2half2_rn(w4.z, w4.w);
    }
    #pragma unroll
    for (int it = 0; it < 8; it++) {
        int idx = tid * 4 + it * 1024;
        int r = idx >> 6, c = idx & 63;
        int grow = row0 + r;
        int n = grow >> 15, rem = grow & 32767;
        int l = rem >> 4, h = rem & 15;
        float4 v4 = *(const float4*)(x + ((size_t)(n * L_S + l) * EMB + h * HD + c));
        *(__half2*)&Xs[r * PITCH + c]     = __floats2half2_rn(v4.x, v4.y);
        *(__half2*)&Xs[r * PITCH + c + 2] = __floats2half2_rn(v4.z, v4.w);
    }
    __syncthreads();

    const int warp = tid >> 5, lane = tid & 31;
    const int g = lane >> 2, t4 = lane & 3;
    const int mw = warp * 16;
    const int lr = lane & 7, lc = lane >> 3;

    uint32_t a[4][4];
    #pragma unroll
    for (int kc = 0; kc < 4; kc++) {
        a[kc][0] = *(const uint32_t*)&Xs[(mw + g    ) * PITCH + kc * 16 + 2 * t4];
        a[kc][1] = *(const uint32_t*)&Xs[(mw + g + 8) * PITCH + kc * 16 + 2 * t4];
        a[kc][2] = *(const uint32_t*)&Xs[(mw + g    ) * PITCH + kc * 16 + 2 * t4 + 8];
        a[kc][3] = *(const uint32_t*)&Xs[(mw + g + 8) * PITCH + kc * 16 + 2 * t4 + 8];
    }

    float o[8][4];
    #pragma unroll
    for (int nt = 0; nt < 8; nt++) { o[nt][0]=o[nt][1]=o[nt][2]=o[nt][3]=0.f; }

    #pragma unroll
    for (int nt = 0; nt < 8; nt++) {
        #pragma unroll
        for (int kc0 = 0; kc0 < 4; kc0 += 2) {
            uint32_t b0, b1, b2, b3;
            ldsm_x4(b0, b1, b2, b3,
                &Ws[(nt * 8 + lr) * PITCH + kc0 * 16 + lc * 8]);
            mma16816(o[nt], a[kc0][0], a[kc0][1], a[kc0][2], a[kc0][3], b0, b1);
            mma16816(o[nt], a[kc0+1][0], a[kc0+1][1], a[kc0+1][2], a[kc0+1][3], b2, b3);
        }
    }

    #pragma unroll
    for (int nt = 0; nt < 8; nt++) {
        int e = nt * 8 + 2 * t4;
        int grow = row0 + mw + g;
        int n = grow >> 15, rem = grow & 32767;
        int l = rem >> 4, h = rem & 15;
        *(__half2*)(out + ((size_t)(n * NH + h) * L_S + l) * HD + e)
            = __floats2half2_rn(o[nt][0], o[nt][1]);
        grow += 8; n = grow >> 15; rem = grow & 32767; l = rem >> 4; h = rem & 15;
        *(__half2*)(out + ((size_t)(n * NH + h) * L_S + l) * HD + e)
            = __floats2half2_rn(o[nt][2], o[nt][3]);
    }
}

// ---------------------------------------------------------------------------
__global__ __launch_bounds__(256) void wo_cvt(const float* __restrict__ w)
{
    int i = (blockIdx.x * 256 + threadIdx.x) * 4;
    float4 v = *(const float4*)(w + i);
    *(__half2*)(g_woh + i)     = __floats2half2_rn(v.x, v.y);
    *(__half2*)(g_woh + i + 2) = __floats2half2_rn(v.z, v.w);
}

// ---------------------------------------------------------------------------
// Kernel 2: flash attention. grid (nh=32, qt=32), block 128 (4 warps).
// BM=64 q rows, BN=64 keys/iter. cp.async double buffer, ldmatrix frags.
// ---------------------------------------------------------------------------
__global__ __launch_bounds__(128) void attn3()
{
    __shared__ __half Ks[2][64 * PITCH];
    __shared__ __half Vs[2][64 * PITCH];

    const int nh = blockIdx.x;
    const int qt = blockIdx.y;
    const int n  = nh >> 4, h = nh & 15;
    const int q0 = qt * 64;

    const __half* Qg = g_qp + (size_t)nh * L_S * HD;
    const __half* Kg = g_kp + (size_t)nh * L_S * HD;
    const __half* Vg = g_vp + (size_t)nh * L_S * HD;

    const int tid = threadIdx.x;
    const int warp = tid >> 5, lane = tid & 31;
    const int g = lane >> 2, t4 = lane & 3;
    const int mw = warp * 16;
    const int lr = lane & 7, lc = lane >> 3;

    // Q A-fragments directly from gmem (one-time)
    uint32_t qa[4][4];
    {
        const __half* Qr0 = Qg + (size_t)(q0 + mw + g    ) * HD;
        const __half* Qr1 = Qg + (size_t)(q0 + mw + g + 8) * HD;
        #pragma unroll
        for (int kc = 0; kc < 4; kc++) {
            qa[kc][0] = *(const uint32_t*)&Qr0[kc * 16 + 2 * t4];
            qa[kc][1] = *(const uint32_t*)&Qr1[kc * 16 + 2 * t4];
            qa[kc][2] = *(const uint32_t*)&Qr0[kc * 16 + 2 * t4 + 8];
            qa[kc][3] = *(const uint32_t*)&Qr1[kc * 16 + 2 * t4 + 8];
        }
    }

    const unsigned char* flags = g_mflag + ((size_t)n * 32 + qt) * 32;
    const uint32_t* Mp = g_mpack + (size_t)n * L_S * 64;

    // tile loader: 64x64 halves K + V, 16B chunks via cp.async
    auto load_kv = [&](int kt, int b) {
        const int k0 = kt * 64;
        #pragma unroll
        for (int it = 0; it < 4; it++) {
            int c = tid + it * 128;        // 0..511
            int r = c >> 3, off = (c & 7) * 8;
            cp16(&Ks[b][r * PITCH + off], &Kg[(size_t)(k0 + r) * HD + off]);
        }
        #pragma unroll
        for (int it = 0; it < 4; it++) {
            int c = tid + it * 128;
            int r = c >> 3, off = (c & 7) * 8;
            cp16(&Vs[b][r * PITCH + off], &Vg[(size_t)(k0 + r) * HD + off]);
        }
        cp_commit();
    };

    float o[8][4];
    #pragma unroll
    for (int ne = 0; ne < 8; ne++) { o[ne][0]=o[ne][1]=o[ne][2]=o[ne][3]=0.f; }
    float mr0 = -1e30f, mr1 = -1e30f, l0 = 0.f, l1 = 0.f;

    load_kv(0, 0);
    load_kv(1, 1);

    const int NT = L_S / 64;
    for (int kt = 0; kt < NT; kt++) {
        const int b = kt & 1;
        const int k0 = kt * 64;

        if (kt == NT - 1) cp_wait<0>(); else cp_wait<1>();
        __syncthreads();

        // GEMM1: S = Q K^T
        float s[8][4];
        #pragma unroll
        for (int nt = 0; nt < 8; nt++) {
            s[nt][0]=s[nt][1]=s[nt][2]=s[nt][3]=0.f;
            #pragma unroll
            for (int kc0 = 0; kc0 < 4; kc0 += 2) {
                uint32_t b0, b1, b2, b3;
                ldsm_x4(b0, b1, b2, b3,
                    &Ks[b][(nt * 8 + lr) * PITCH + kc0 * 16 + lc * 8]);
                mma16816(s[nt], qa[kc0][0], qa[kc0][1], qa[kc0][2], qa[kc0][3], b0, b1);
                mma16816(s[nt], qa[kc0+1][0], qa[kc0+1][1], qa[kc0+1][2], qa[kc0+1][3], b2, b3);
            }
        }

        // mask (skipped when tile is all-ones)
        if (!flags[kt]) {
            uint64_t w0 = *(const uint64_t*)&Mp[(size_t)(q0 + mw + g    ) * 64 + (k0 >> 5)];
            uint64_t w1 = *(const uint64_t*)&Mp[(size_t)(q0 + mw + g + 8) * 64 + (k0 >> 5)];
            #pragma unroll
            for (int nt = 0; nt < 8; nt++) {
                int bit = nt * 8 + 2 * t4;
                if (!((w0 >> bit) & 1))       s[nt][0] = -1e20f;
                if (!((w0 >> (bit + 1)) & 1)) s[nt][1] = -1e20f;
                if (!((w1 >> bit) & 1))       s[nt][2] = -1e20f;
                if (!((w1 >> (bit + 1)) & 1)) s[nt][3] = -1e20f;
            }
        }

        // online softmax (rows g, g+8)
        float mx0 = s[0][0], mx1 = s[0][2];
        #pragma unroll
        for (int nt = 0; nt < 8; nt++) {
            mx0 = fmaxf(mx0, fmaxf(s[nt][0], s[nt][1]));
            mx1 = fmaxf(mx1, fmaxf(s[nt][2], s[nt][3]));
        }
        mx0 = fmaxf(mx0, __shfl_xor_sync(0xffffffffu, mx0, 1));
        mx0 = fmaxf(mx0, __shfl_xor_sync(0xffffffffu, mx0, 2));
        mx1 = fmaxf(mx1, __shfl_xor_sync(0xffffffffu, mx1, 1));
        mx1 = fmaxf(mx1, __shfl_xor_sync(0xffffffffu, mx1, 2));

        float mn0 = fmaxf(mr0, mx0), mn1 = fmaxf(mr1, mx1);
        float c0 = exp2_fast((mr0 - mn0) * CEXP);
        float c1 = exp2_fast((mr1 - mn1) * CEXP);
        mr0 = mn0; mr1 = mn1;

        float sum0 = 0.f, sum1 = 0.f;
        #pragma unroll
        for (int nt = 0; nt < 8; nt++) {
            s[nt][0] = exp2_fast((s[nt][0] - mn0) * CEXP); sum0 += s[nt][0];
            s[nt][1] = exp2_fast((s[nt][1] - mn0) * CEXP); sum0 += s[nt][1];
            s[nt][2] = exp2_fast((s[nt][2] - mn1) * CEXP); sum1 += s[nt][2];
            s[nt][3] = exp2_fast((s[nt][3] - mn1) * CEXP); sum1 += s[nt][3];
        }
        sum0 += __shfl_xor_sync(0xffffffffu, sum0, 1);
        sum0 += __shfl_xor_sync(0xffffffffu, sum0, 2);
        sum1 += __shfl_xor_sync(0xffffffffu, sum1, 1);
        sum1 += __shfl_xor_sync(0xffffffffu, sum1, 2);
        l0 = l0 * c0 + sum0;
        l1 = l1 * c1 + sum1;

        #pragma unroll
        for (int ne = 0; ne < 8; ne++) {
            o[ne][0] *= c0; o[ne][1] *= c0;
            o[ne][2] *= c1; o[ne][3] *= c1;
        }

        // P A-fragments from registers
        uint32_t pa[4][4];
        #pragma unroll
        for (int kc = 0; kc < 4; kc++) {
            pa[kc][0] = packh2(s[2 * kc    ][0], s[2 * kc    ][1]);
            pa[kc][1] = packh2(s[2 * kc    ][2], s[2 * kc    ][3]);
            pa[kc][2] = packh2(s[2 * kc + 1][0], s[2 * kc + 1][1]);
            pa[kc][3] = packh2(s[2 * kc + 1][2], s[2 * kc + 1][3]);
        }

        // GEMM2: O += P V  (B-frags via ldmatrix.trans on row-major V)
        #pragma unroll
        for (int ne = 0; ne < 8; ne++) {
            #pragma unroll
            for (int kc0 = 0; kc0 < 4; kc0 += 2) {
                uint32_t b0, b1, b2, b3;
                ldsm_x4_t(b0, b1, b2, b3,
                    &Vs[b][(kc0 * 16 + lane) * PITCH + ne * 8]);
                mma16816(o[ne], pa[kc0][0], pa[kc0][1], pa[kc0][2], pa[kc0][3], b0, b1);
                mma16816(o[ne], pa[kc0+1][0], pa[kc0+1][1], pa[kc0+1][2], pa[kc0+1][3], b2, b3);
            }
        }

        __syncthreads();                 // all warps done with buffer b
        if (kt + 2 < NT) load_kv(kt + 2, b);
    }

    float inv0 = 1.f / l0, inv1 = 1.f / l1;
    int row = q0 + mw + g;
    __half* base0 = g_att + ((size_t)n * L_S + row) * EMB + h * HD;
    __half* base1 = base0 + (size_t)8 * EMB;
    #pragma unroll
    for (int ne = 0; ne < 8; ne++) {
        int e = ne * 8 + 2 * t4;
        *(__half2*)(base0 + e) = __floats2half2_rn(o[ne][0] * inv0, o[ne][1] * inv0);
        *(__half2*)(base1 + e) = __floats2half2_rn(o[ne][2] * inv1, o[ne][3] * inv1);
    }
}

// ---------------------------------------------------------------------------
// Kernel 3: out projection, cp.async double-buffered + ldmatrix.
// grid (32 m-tiles, 16 e-tiles), block 256. BM=128, BN=64, K-tile 64.
// ---------------------------------------------------------------------------
__global__ __launch_bounds__(256) void out_mma2(
    const float* __restrict__ bo, float* __restrict__ out)
{
    extern __shared__ __half sm[];
    __half* As[2] = { sm, sm + 128 * PITCH };
    __half* Bs[2] = { sm + 2 * 128 * PITCH, sm + 2 * 128 * PITCH + 64 * PITCH };

    const int m0 = blockIdx.x * 128;
    const int e0 = blockIdx.y * 64;
    const int tid = threadIdx.x;
    const int warp = tid >> 5, lane = tid & 31;
    const int g = lane >> 2, t4 = lane & 3;
    const int mw = warp * 16;
    const int lr = lane & 7, lc = lane >> 3;

    auto load_ab = [&](int f, int b) {
        const int f0 = f * 64;
        #pragma unroll
        for (int it = 0; it < 4; it++) {
            int c = tid + it * 256;        // 0..1023
            int r = c >> 3, off = (c & 7) * 8;
            cp16(&As[b][r * PITCH + off], &g_att[(size_t)(m0 + r) * EMB + f0 + off]);
        }
        #pragma unroll
        for (int it = 0; it < 2; it++) {
            int c = tid + it * 256;        // 0..511
            int r = c >> 3, off = (c & 7) * 8;
            cp16(&Bs[b][r * PITCH + off], &g_woh[(size_t)(e0 + r) * EMB + f0 + off]);
        }
        cp_commit();
    };

    float o[8][4];
    #pragma unroll
    for (int nt = 0; nt < 8; nt++) { o[nt][0]=o[nt][1]=o[nt][2]=o[nt][3]=0.f; }

    load_ab(0, 0);
    load_ab(1, 1);

    const int NF = EMB / 64;
    for (int f = 0; f < NF; f++) {
        const int b = f & 1;
        if (f == NF - 1) cp_wait<0>(); else cp_wait<1>();
        __syncthreads();

        uint32_t a[4][4];
        #pragma unroll
        for (int kc = 0; kc < 4; kc++) {
            ldsm_x4(a[kc][0], a[kc][1], a[kc][2], a[kc][3],
                &As[b][(mw + lr + ((lane >> 3) & 1) * 8) * PITCH
                       + kc * 16 + (lane >> 4) * 8]);
        }
        #pragma unroll
        for (int nt = 0; nt < 8; nt++) {
            #pragma unroll
            for (int kc0 = 0; kc0 < 4; kc0 += 2) {
                uint32_t b0, b1, b2, b3;
                ldsm_x4(b0, b1, b2, b3,
                    &Bs[b][(nt * 8 + lr) * PITCH + kc0 * 16 + lc * 8]);
                mma16816(o[nt], a[kc0][0], a[kc0][1], a[kc0][2], a[kc0][3], b0, b1);
                mma16816(o[nt], a[kc0+1][0], a[kc0+1][1], a[kc0+1][2], a[kc0+1][3], b2, b3);
            }
        }

        __syncthreads();
        if (f + 2 < NF) load_ab(f + 2, b);
    }

    #pragma unroll
    for (int nt = 0; nt < 8; nt++) {
        int e = e0 + nt * 8 + 2 * t4;
        float b0v = bo[e], b1v = bo[e + 1];
        float2* d0 = (float2*)(out + (size_t)(m0 + mw + g    ) * EMB + e);
        float2* d1 = (float2*)(out + (size_t)(m0 + mw + g + 8) * EMB + e);
        *d0 = make_float2(o[nt][0] + b0v, o[nt][1] + b1v);
        *d1 = make_float2(o[nt][2] + b0v, o[nt][3] + b1v);
    }
}

// ---------------------------------------------------------------------------
extern "C" void kernel_launch(void* const* d_in, const int* in_sizes, int n_in,
                              void* d_out, int out_size)
{
    const float* values  = (const float*)d_in[0];
    const float* keys    = (const float*)d_in[1];
    const float* queries = (const float*)d_in[2];
    const int*   mask    = (const int*)  d_in[3];
    const float* Wv      = (const float*)d_in[4];
    const float* Wk      = (const float*)d_in[5];
    const float* Wq      = (const float*)d_in[6];
    const float* Wo      = (const float*)d_in[7];
    const float* bo      = (const float*)d_in[8];
    float* out = (float*)d_out;

    proj_mma<<<dim3(512, 3), 256>>>(queries, keys, values, Wq, Wk, Wv);
    wo_cvt<<<1024, 256>>>(Wo);
    mask_pack<<<N_B * L_S * 64 / 256, 256>>>(mask);
    mask_flag<<<N_B * 32 * 32, 128>>>();

    attn3<<<dim3(N_B * NH, L_S / 64), 128>>>();

    const int smem_out = (2 * 128 * PITCH + 2 * 64 * PITCH) * sizeof(__half);
    cudaFuncSetAttribute(out_mma2, cudaFuncAttributeMaxDynamicSharedMemorySize, smem_out);
    out_mma2<<<dim3((N_B * L_S) / 128, EMB / 64), 256, smem_out>>>(bo, out);
}